// round 1
// baseline (speedup 1.0000x reference)
#include <cuda_runtime.h>
#include <math.h>

// DSAFTNKSPLLoss — n = 8192 fixed.
// Stage 1: single-block bitonic argsort of e = log(dur+1e-32) - theta,
//          scatter ev/th through the inverse permutation (reference semantics).
// Stage 2: O(n^2) pair kernel: Gaussian pdf sum (cond_E) + normal cdf sum (surv).
//          cdf via Zelen-Severo (A&S 26.2.17) reusing exp(-d^2/2): abs err <= 7.5e-8.
// Stage 3: deterministic tree reduction to the scalar loss.

#define NV 8192
#define SORT_T 1024
#define ROWS_PER_BLOCK 4

__device__ float g_es[NV];       // e sorted ascending
__device__ float g_ev[NV];       // events[inv[k]]  (float)
__device__ float g_th[NV];       // theta[inv[k]]
__device__ float g_rowloss[NV];  // per-row loss terms

__global__ void sort_prep_kernel(const float* __restrict__ log_h,
                                 const float* __restrict__ dur,
                                 const int* __restrict__ events) {
    extern __shared__ unsigned long long key[];
    const int tid = threadIdx.x;

    // Build sortable keys: monotone-mapped float bits in high 32, index in low 32.
#pragma unroll
    for (int m = 0; m < NV / SORT_T; m++) {
        int i = tid + m * SORT_T;
        float e = logf(dur[i] + 1e-32f) - log_h[i];
        unsigned int u = __float_as_uint(e);
        u = (u & 0x80000000u) ? ~u : (u | 0x80000000u);
        key[i] = ((unsigned long long)u << 32) | (unsigned int)i;
    }
    __syncthreads();

    // Bitonic sort, ascending.
    for (int k = 2; k <= NV; k <<= 1) {
        for (int j = k >> 1; j > 0; j >>= 1) {
#pragma unroll
            for (int m = 0; m < NV / SORT_T; m++) {
                int i = tid + m * SORT_T;
                int ixj = i ^ j;
                if (ixj > i) {
                    unsigned long long a = key[i];
                    unsigned long long b = key[ixj];
                    bool up = ((i & k) == 0);
                    if ((a > b) == up) { key[i] = b; key[ixj] = a; }
                }
            }
            __syncthreads();
        }
    }

    // Emit: e_sorted[k]; and for orig index o = perm[k], rank(o) = k, so
    // ev[o] = events[k], th[o] = theta[k]  (reference gathers by INVERSE perm).
#pragma unroll
    for (int m = 0; m < NV / SORT_T; m++) {
        int kpos = tid + m * SORT_T;
        unsigned long long kk = key[kpos];
        int orig = (int)(kk & 0xffffffffULL);
        unsigned int u = (unsigned int)(kk >> 32);
        u = (u & 0x80000000u) ? (u & 0x7fffffffu) : ~u;  // inverse of the monotone map
        g_es[kpos] = __uint_as_float(u);
        g_ev[orig] = (float)events[kpos];
        g_th[orig] = log_h[kpos];
    }
}

// 1 warp per block, 4 rows per warp, lanes stride columns.
__global__ void __launch_bounds__(32) pair_kernel() {
    const int lane = threadIdx.x;
    const int r = blockIdx.x * ROWS_PER_BLOCK;

    float er[ROWS_PER_BLOCK], c[ROWS_PER_BLOCK], sv[ROWS_PER_BLOCK];
#pragma unroll
    for (int m = 0; m < ROWS_PER_BLOCK; m++) {
        er[m] = g_es[r + m];
        c[m] = 0.0f;
        sv[m] = 0.0f;
    }

    const float NEXP = -0.72134752044448f;  // -0.5 * log2(e)

    for (int j = lane; j < NV; j += 32) {
        float ej = __ldg(&g_es[j]);
        float vj = __ldg(&g_ev[j]);
#pragma unroll
        for (int m = 0; m < ROWS_PER_BLOCK; m++) {
            float d  = er[m] - ej;               // diff_ij
            float ex = exp2f(d * d * NEXP);      // exp(-0.5 d^2)
            c[m] = fmaf(ex, vj, c[m]);           // pdf sum (x 1/sqrt(2pi) folded later)

            // Normal cdf via Zelen-Severo, phi folded into coefficients:
            // q = 1 - Phi(|d|) = ex * t * (B1 + t(B2 + t(B3 + t(B4 + t*B5))))
            float den = fmaf(0.2316419f, fabsf(d), 1.0f);
            float t;
            asm("rcp.approx.f32 %0, %1;" : "=f"(t) : "f"(den));
            float p = fmaf(t, 0.530702685f, -0.726576002f);
            p = fmaf(t, p, 0.710706864f);
            p = fmaf(t, p, -0.142248367f);
            p = fmaf(t, p, 0.127414794f);
            float q = ex * (t * p);
            // cdf(d) = 0.5 + copysign(0.5 - q, d); accumulate the signed part,
            // fold the +0.5 per element in at the end (0.5 total after /n).
            sv[m] += copysignf(0.5f - q, d);
        }
    }

    // Warp reduction of the 8 accumulators.
#pragma unroll
    for (int m = 0; m < ROWS_PER_BLOCK; m++) {
#pragma unroll
        for (int off = 16; off > 0; off >>= 1) {
            c[m]  += __shfl_down_sync(0xffffffffu, c[m], off);
            sv[m] += __shfl_down_sync(0xffffffffu, sv[m], off);
        }
    }

    if (lane == 0) {
#pragma unroll
        for (int m = 0; m < ROWS_PER_BLOCK; m++) {
            // cond_E = sum(pdf*ev)/(n) * (1/sqrt(2pi)) + n*1e-32
            float cond = fmaf(c[m], 0.3989422804014327f / 8192.0f, 8.192e-29f);
            // surv = mean(cdf) = 0.5 + mean(signed part)
            float surv = fmaf(sv[m], 1.0f / 8192.0f, 0.5f);
            g_rowloss[r + m] =
                (logf(cond) - logf(surv) + g_th[r + m]) * g_ev[r + m];
        }
    }
}

__global__ void reduce_kernel(float* __restrict__ out) {
    __shared__ float sm[1024];
    const int tid = threadIdx.x;
    float a = 0.0f;
    for (int i = tid; i < NV; i += 1024) a += g_rowloss[i];
    sm[tid] = a;
    __syncthreads();
    for (int s = 512; s > 0; s >>= 1) {
        if (tid < s) sm[tid] += sm[tid + s];
        __syncthreads();
    }
    if (tid == 0) out[0] = -sm[0] * (1.0f / 8192.0f);
}

extern "C" void kernel_launch(void* const* d_in, const int* in_sizes, int n_in,
                              void* d_out, int out_size) {
    const float* log_h  = (const float*)d_in[0];
    const float* dur    = (const float*)d_in[1];
    const int*   events = (const int*)d_in[2];
    float* out = (float*)d_out;

    cudaFuncSetAttribute(sort_prep_kernel,
                         cudaFuncAttributeMaxDynamicSharedMemorySize, NV * 8);
    sort_prep_kernel<<<1, SORT_T, NV * 8>>>(log_h, dur, events);
    pair_kernel<<<NV / ROWS_PER_BLOCK, 32>>>();
    reduce_kernel<<<1, 1024>>>(out);
}

// round 2
// speedup vs baseline: 1.0930x; 1.0930x over previous
#include <cuda_runtime.h>
#include <math.h>

// DSAFTNKSPLLoss — n = 8192 fixed.
// Stage A: prep — e = log(dur+1e-32) - theta, build sortable u64 keys.
// Stage B: rank-by-counting (replaces the 88us single-block bitonic sort):
//          rank(o) = #{p : key_p < key_o}; scatter e_sorted, gather ev/th.
// Stage C: O(n^2) pair kernel: Gaussian pdf sum (cond_E) + normal cdf sum (surv).
//          cdf via Zelen-Severo (A&S 26.2.17) reusing exp(-d^2/2): abs err <= 7.5e-8.
// Stage D: deterministic tree reduction to the scalar loss.

#define NV 8192
#define ROWS_PER_BLOCK 4   // pair kernel rows per warp
#define ROWS_R 8           // rank kernel rows per warp

__device__ unsigned long long g_key[NV];
__device__ float g_e[NV];        // e in original order
__device__ float g_es[NV];       // e sorted ascending
__device__ float g_ev[NV];       // events[rank(o)]  (float)
__device__ float g_th[NV];       // theta[rank(o)]
__device__ float g_rowloss[NV];  // per-row loss terms

__global__ void prep_kernel(const float* __restrict__ log_h,
                            const float* __restrict__ dur) {
    int i = blockIdx.x * blockDim.x + threadIdx.x;
    if (i >= NV) return;
    float e = logf(dur[i] + 1e-32f) - log_h[i];
    unsigned int u = __float_as_uint(e);
    u = (u & 0x80000000u) ? ~u : (u | 0x80000000u);  // monotone map to uint
    g_e[i] = e;
    g_key[i] = ((unsigned long long)u << 32) | (unsigned int)i;
}

// rank(o) = count of keys strictly less; keys unique (index in low bits),
// lexicographic (value, index) order == jax stable argsort.
__global__ void __launch_bounds__(32) rank_kernel(const float* __restrict__ log_h,
                                                  const int* __restrict__ events) {
    const int lane = threadIdx.x;
    const int r0 = blockIdx.x * ROWS_R;

    unsigned long long ko[ROWS_R];
    int cnt[ROWS_R];
#pragma unroll
    for (int m = 0; m < ROWS_R; m++) {
        ko[m] = g_key[r0 + m];
        cnt[m] = 0;
    }

    for (int p = lane; p < NV; p += 32) {
        unsigned long long kp = __ldg(&g_key[p]);
#pragma unroll
        for (int m = 0; m < ROWS_R; m++) cnt[m] += (kp < ko[m]);
    }

#pragma unroll
    for (int m = 0; m < ROWS_R; m++)
        cnt[m] = __reduce_add_sync(0xffffffffu, cnt[m]);

    if (lane < ROWS_R) {
        int o = r0 + lane;
        int r = cnt[lane];                 // rank(o)
        g_es[r] = g_e[o];                  // scatter sorted values
        g_ev[o] = (float)__ldg(&events[r]);
        g_th[o] = __ldg(&log_h[r]);
    }
}

// 1 warp per block, 4 rows per warp, lanes stride columns.
__global__ void __launch_bounds__(32) pair_kernel() {
    const int lane = threadIdx.x;
    const int r = blockIdx.x * ROWS_PER_BLOCK;

    float er[ROWS_PER_BLOCK], c[ROWS_PER_BLOCK], sv[ROWS_PER_BLOCK];
#pragma unroll
    for (int m = 0; m < ROWS_PER_BLOCK; m++) {
        er[m] = g_es[r + m];
        c[m] = 0.0f;
        sv[m] = 0.0f;
    }

    const float NEXP = -0.72134752044448f;  // -0.5 * log2(e)

    for (int j = lane; j < NV; j += 32) {
        float ej = __ldg(&g_es[j]);
        float vj = __ldg(&g_ev[j]);
#pragma unroll
        for (int m = 0; m < ROWS_PER_BLOCK; m++) {
            float d  = er[m] - ej;               // diff_ij
            float ex = exp2f(d * d * NEXP);      // exp(-0.5 d^2)
            c[m] = fmaf(ex, vj, c[m]);           // pdf sum (x 1/sqrt(2pi) folded later)

            // q = 1 - Phi(|d|) = ex * t * poly(t),  t = 1/(1 + 0.2316419|d|)
            float den = fmaf(0.2316419f, fabsf(d), 1.0f);
            float t;
            asm("rcp.approx.f32 %0, %1;" : "=f"(t) : "f"(den));
            float p = fmaf(t, 0.530702685f, -0.726576002f);
            p = fmaf(t, p, 0.710706864f);
            p = fmaf(t, p, -0.142248367f);
            p = fmaf(t, p, 0.127414794f);
            float q = ex * (t * p);
            // cdf(d) = 0.5 + copysign(0.5 - q, d); fold the +0.5 in at the end.
            sv[m] += copysignf(0.5f - q, d);
        }
    }

#pragma unroll
    for (int m = 0; m < ROWS_PER_BLOCK; m++) {
#pragma unroll
        for (int off = 16; off > 0; off >>= 1) {
            c[m]  += __shfl_down_sync(0xffffffffu, c[m], off);
            sv[m] += __shfl_down_sync(0xffffffffu, sv[m], off);
        }
    }

    if (lane == 0) {
#pragma unroll
        for (int m = 0; m < ROWS_PER_BLOCK; m++) {
            float cond = fmaf(c[m], 0.3989422804014327f / 8192.0f, 8.192e-29f);
            float surv = fmaf(sv[m], 1.0f / 8192.0f, 0.5f);
            g_rowloss[r + m] =
                (logf(cond) - logf(surv) + g_th[r + m]) * g_ev[r + m];
        }
    }
}

__global__ void reduce_kernel(float* __restrict__ out) {
    __shared__ float sm[1024];
    const int tid = threadIdx.x;
    float a = 0.0f;
    for (int i = tid; i < NV; i += 1024) a += g_rowloss[i];
    sm[tid] = a;
    __syncthreads();
    for (int s = 512; s > 0; s >>= 1) {
        if (tid < s) sm[tid] += sm[tid + s];
        __syncthreads();
    }
    if (tid == 0) out[0] = -sm[0] * (1.0f / 8192.0f);
}

extern "C" void kernel_launch(void* const* d_in, const int* in_sizes, int n_in,
                              void* d_out, int out_size) {
    const float* log_h  = (const float*)d_in[0];
    const float* dur    = (const float*)d_in[1];
    const int*   events = (const int*)d_in[2];
    float* out = (float*)d_out;

    prep_kernel<<<NV / 256, 256>>>(log_h, dur);
    rank_kernel<<<NV / ROWS_R, 32>>>(log_h, events);
    pair_kernel<<<NV / ROWS_PER_BLOCK, 32>>>();
    reduce_kernel<<<1, 1024>>>(out);
}

// round 3
// speedup vs baseline: 1.7058x; 1.5606x over previous
#include <cuda_runtime.h>
#include <math.h>

// DSAFTNKSPLLoss — n = 8192 fixed.
// prep    : e = log(dur+1e-32) - theta, sortable u64 key, zero rank counters.
// rank    : rank(o) = #{p : key_p < key_o} via 4-way column-split counting,
//           integer atomicAdd partials (exact -> deterministic).
// scatter : e_sorted[rank]=e, ev[o]=events[rank], th[o]=log_h[rank].
// pair    : O(n^2) Gaussian pdf sum + normal cdf sum, f32x2-packed (FFMA2),
//           cdf via Zelen-Severo reusing exp(-d^2/2).
// reduce  : deterministic tree reduction to the scalar loss.

#define NV 8192
#define ROWS_P 8      // pair kernel rows per warp (4 packed pairs)
#define ROWS_R 8      // rank kernel rows per warp
#define CHUNKS_R 4    // rank kernel column splits

typedef unsigned long long ull;

__device__ ull   g_key[NV];
__device__ int   g_rank[NV];
__device__ float g_e[NV];
__device__ float g_es[NV];
__device__ float g_ev[NV];
__device__ float g_th[NV];
__device__ float g_rowloss[NV];

// ---------- f32x2 helpers ----------
static __device__ __forceinline__ ull pk(float a, float b) {
    ull r; asm("mov.b64 %0, {%1, %2};" : "=l"(r) : "f"(a), "f"(b)); return r;
}
static __device__ __forceinline__ void unpk(float& a, float& b, ull x) {
    asm("mov.b64 {%0, %1}, %2;" : "=f"(a), "=f"(b) : "l"(x));
}
static __device__ __forceinline__ ull add2(ull a, ull b) {
    ull r; asm("add.rn.f32x2 %0, %1, %2;" : "=l"(r) : "l"(a), "l"(b)); return r;
}
static __device__ __forceinline__ ull mul2(ull a, ull b) {
    ull r; asm("mul.rn.f32x2 %0, %1, %2;" : "=l"(r) : "l"(a), "l"(b)); return r;
}
static __device__ __forceinline__ ull fma2(ull a, ull b, ull c) {
    ull r; asm("fma.rn.f32x2 %0, %1, %2, %3;" : "=l"(r) : "l"(a), "l"(b), "l"(c)); return r;
}
static __device__ __forceinline__ float ex2a(float x) {
    float r; asm("ex2.approx.f32 %0, %1;" : "=f"(r) : "f"(x)); return r;
}
static __device__ __forceinline__ float rcpa(float x) {
    float r; asm("rcp.approx.f32 %0, %1;" : "=f"(r) : "f"(x)); return r;
}
// res = s | (d & 0x80000000)  (s >= 0, so this is copysign(s, d))
static __device__ __forceinline__ float sgnor(float s, float d) {
    unsigned r;
    asm("lop3.b32 %0, %1, %2, 0x80000000, 0xF8;"
        : "=r"(r) : "r"(__float_as_uint(s)), "r"(__float_as_uint(d)));
    return __uint_as_float(r);
}

__global__ void prep_kernel(const float* __restrict__ log_h,
                            const float* __restrict__ dur) {
    int i = blockIdx.x * blockDim.x + threadIdx.x;
    if (i >= NV) return;
    float e = logf(dur[i] + 1e-32f) - log_h[i];
    unsigned u = __float_as_uint(e);
    u = (u & 0x80000000u) ? ~u : (u | 0x80000000u);  // monotone map
    g_e[i] = e;
    g_key[i] = ((ull)u << 32) | (unsigned)i;
    g_rank[i] = 0;
}

__global__ void __launch_bounds__(32) rank_kernel() {
    const int lane = threadIdx.x;
    const int r0 = (blockIdx.x / CHUNKS_R) * ROWS_R;
    const int p0 = (blockIdx.x % CHUNKS_R) * (NV / CHUNKS_R);

    ull ko[ROWS_R];
    int cnt[ROWS_R];
#pragma unroll
    for (int m = 0; m < ROWS_R; m++) { ko[m] = g_key[r0 + m]; cnt[m] = 0; }

#pragma unroll 4
    for (int t = 0; t < NV / CHUNKS_R / 32; t++) {
        ull kp = __ldg(&g_key[p0 + lane + t * 32]);
#pragma unroll
        for (int m = 0; m < ROWS_R; m++) cnt[m] += (kp < ko[m]);
    }

#pragma unroll
    for (int m = 0; m < ROWS_R; m++)
        cnt[m] = __reduce_add_sync(0xffffffffu, cnt[m]);

    if (lane < ROWS_R) atomicAdd(&g_rank[r0 + lane], cnt[lane]);
}

__global__ void scatter_kernel(const float* __restrict__ log_h,
                               const int* __restrict__ events) {
    int o = blockIdx.x * blockDim.x + threadIdx.x;
    if (o >= NV) return;
    int r = g_rank[o];
    g_es[r] = g_e[o];
    g_ev[o] = (float)__ldg(&events[r]);
    g_th[o] = __ldg(&log_h[r]);
}

// 1 warp per block, 8 rows (4 f32x2 pairs) per warp, lanes stride columns.
__global__ void __launch_bounds__(32) pair_kernel() {
    const int lane = threadIdx.x;
    const int r = blockIdx.x * ROWS_P;

    ull er2[4], c2[4], sv2[4];
#pragma unroll
    for (int m = 0; m < 4; m++) {
        er2[m] = pk(g_es[r + 2 * m], g_es[r + 2 * m + 1]);
        c2[m] = pk(0.0f, 0.0f);
        sv2[m] = pk(0.0f, 0.0f);
    }

    const float NEXP = -0.72134752044448f;   // -0.5 * log2(e)
    const ull NEXP2 = pk(NEXP, NEXP);
    const ull A2    = pk(0.2316419f, 0.2316419f);
    const ull ONE2  = pk(1.0f, 1.0f);
    // Zelen-Severo coefficients, NEGATED (so s = fma(ex, t*p, 0.5) = 0.5 - q)
    const ull B5n = pk(-0.530702685f, -0.530702685f);
    const ull B4n = pk( 0.726576002f,  0.726576002f);
    const ull B3n = pk(-0.710706864f, -0.710706864f);
    const ull B2n = pk( 0.142248367f,  0.142248367f);
    const ull B1n = pk(-0.127414794f, -0.127414794f);
    const ull HALF2 = pk(0.5f, 0.5f);
    const ull ABSM  = 0x7fffffff7fffffffULL;

    for (int j = lane; j < NV; j += 32) {
        float ej = __ldg(&g_es[j]);
        float vj = __ldg(&g_ev[j]);
        ull nej2 = pk(-ej, -ej);
        ull vj2  = pk(vj, vj);
#pragma unroll
        for (int m = 0; m < 4; m++) {
            ull d  = add2(er2[m], nej2);          // diff (packed 2 rows)
            ull dd = mul2(d, d);
            ull a  = mul2(dd, NEXP2);
            float alo, ahi; unpk(alo, ahi, a);
            ull ex = pk(ex2a(alo), ex2a(ahi));    // exp(-d^2/2)
            c2[m] = fma2(ex, vj2, c2[m]);         // pdf accumulation

            ull ad  = d & ABSM;                   // |d|
            ull den = fma2(ad, A2, ONE2);         // 1 + 0.2316419|d|
            float dnlo, dnhi; unpk(dnlo, dnhi, den);
            ull t = pk(rcpa(dnlo), rcpa(dnhi));
            ull p = fma2(t, B5n, B4n);
            p = fma2(t, p, B3n);
            p = fma2(t, p, B2n);
            p = fma2(t, p, B1n);
            ull tp = mul2(t, p);
            ull s  = fma2(ex, tp, HALF2);         // 0.5 - q, q = 1-Phi(|d|)

            float slo, shi, dlo, dhi;
            unpk(slo, shi, s);
            unpk(dlo, dhi, d);
            sv2[m] = add2(sv2[m], pk(sgnor(slo, dlo), sgnor(shi, dhi)));
        }
    }

    float c[ROWS_P], sv[ROWS_P];
#pragma unroll
    for (int m = 0; m < 4; m++) {
        unpk(c[2 * m], c[2 * m + 1], c2[m]);
        unpk(sv[2 * m], sv[2 * m + 1], sv2[m]);
    }
#pragma unroll
    for (int k = 0; k < ROWS_P; k++) {
#pragma unroll
        for (int off = 16; off > 0; off >>= 1) {
            c[k]  += __shfl_down_sync(0xffffffffu, c[k], off);
            sv[k] += __shfl_down_sync(0xffffffffu, sv[k], off);
        }
    }

    if (lane == 0) {
#pragma unroll
        for (int k = 0; k < ROWS_P; k++) {
            float cond = fmaf(c[k], 0.3989422804014327f / 8192.0f, 8.192e-29f);
            float surv = fmaf(sv[k], 1.0f / 8192.0f, 0.5f);
            g_rowloss[r + k] = (logf(cond) - logf(surv) + g_th[r + k]) * g_ev[r + k];
        }
    }
}

__global__ void __launch_bounds__(256) reduce_kernel(float* __restrict__ out) {
    __shared__ float sm[8];
    const int tid = threadIdx.x;
    const float4* v = (const float4*)g_rowloss;
    float a = 0.0f;
#pragma unroll
    for (int t = 0; t < NV / 4 / 256; t++) {
        float4 x = v[tid + t * 256];
        a += (x.x + x.y) + (x.z + x.w);
    }
#pragma unroll
    for (int off = 16; off > 0; off >>= 1)
        a += __shfl_down_sync(0xffffffffu, a, off);
    if ((tid & 31) == 0) sm[tid >> 5] = a;
    __syncthreads();
    if (tid == 0) {
        float s = 0.0f;
#pragma unroll
        for (int w = 0; w < 8; w++) s += sm[w];
        out[0] = -s * (1.0f / 8192.0f);
    }
}

extern "C" void kernel_launch(void* const* d_in, const int* in_sizes, int n_in,
                              void* d_out, int out_size) {
    const float* log_h  = (const float*)d_in[0];
    const float* dur    = (const float*)d_in[1];
    const int*   events = (const int*)d_in[2];
    float* out = (float*)d_out;

    prep_kernel<<<NV / 256, 256>>>(log_h, dur);
    rank_kernel<<<(NV / ROWS_R) * CHUNKS_R, 32>>>();
    scatter_kernel<<<NV / 256, 256>>>(log_h, events);
    pair_kernel<<<NV / ROWS_P, 32>>>();
    reduce_kernel<<<1, 256>>>(out);
}

// round 4
// speedup vs baseline: 2.1405x; 1.2549x over previous
#include <cuda_runtime.h>
#include <math.h>

// DSAFTNKSPLLoss — n = 8192 fixed.
// prep    : e = log(dur+1e-32) - theta, sortable u64 key.
// rank    : rank(o) = #{p : key_p < key_o}, 4-way column-split counting.
// scatter : e_sorted[rank]=e, ev[o]=events[rank], th[o]=log_h[rank].
// pair    : O(n^2) Gaussian pdf + normal cdf sums, f32x2-packed, columns split
//           4-way across blocks; per-(chunk,row) partials (no atomics).
// finalize: sum 4 partials per row -> row loss.
// reduce  : deterministic tree reduction to the scalar loss.

#define NV 8192
#define ROWS_P 8      // pair kernel rows per warp (4 packed pairs)
#define CHUNKS_P 4    // pair kernel column splits
#define ROWS_R 8      // rank kernel rows per warp
#define CHUNKS_R 4    // rank kernel column splits

typedef unsigned long long ull;

__device__ ull   g_key[NV];
__device__ int   g_rank[NV];
__device__ float g_e[NV];
__device__ float g_es[NV];
__device__ float g_ev[NV];
__device__ float g_th[NV];
__device__ float g_pc[CHUNKS_P * NV];   // pdf partials
__device__ float g_psv[CHUNKS_P * NV];  // signed-cdf partials
__device__ float g_rowloss[NV];

// ---------- f32x2 helpers ----------
static __device__ __forceinline__ ull pk(float a, float b) {
    ull r; asm("mov.b64 %0, {%1, %2};" : "=l"(r) : "f"(a), "f"(b)); return r;
}
static __device__ __forceinline__ void unpk(float& a, float& b, ull x) {
    asm("mov.b64 {%0, %1}, %2;" : "=f"(a), "=f"(b) : "l"(x));
}
static __device__ __forceinline__ ull add2(ull a, ull b) {
    ull r; asm("add.rn.f32x2 %0, %1, %2;" : "=l"(r) : "l"(a), "l"(b)); return r;
}
static __device__ __forceinline__ ull mul2(ull a, ull b) {
    ull r; asm("mul.rn.f32x2 %0, %1, %2;" : "=l"(r) : "l"(a), "l"(b)); return r;
}
static __device__ __forceinline__ ull fma2(ull a, ull b, ull c) {
    ull r; asm("fma.rn.f32x2 %0, %1, %2, %3;" : "=l"(r) : "l"(a), "l"(b), "l"(c)); return r;
}
static __device__ __forceinline__ float ex2a(float x) {
    float r; asm("ex2.approx.f32 %0, %1;" : "=f"(r) : "f"(x)); return r;
}
static __device__ __forceinline__ float rcpa(float x) {
    float r; asm("rcp.approx.f32 %0, %1;" : "=f"(r) : "f"(x)); return r;
}
// s | (d & 0x80000000)   (s >= 0 -> copysign(s, d))
static __device__ __forceinline__ float sgnor(float s, float d) {
    unsigned r;
    asm("lop3.b32 %0, %1, %2, 0x80000000, 0xF8;"
        : "=r"(r) : "r"(__float_as_uint(s)), "r"(__float_as_uint(d)));
    return __uint_as_float(r);
}

__global__ void prep_kernel(const float* __restrict__ log_h,
                            const float* __restrict__ dur) {
    int i = blockIdx.x * blockDim.x + threadIdx.x;
    if (i >= NV) return;
    float e = logf(dur[i] + 1e-32f) - log_h[i];
    unsigned u = __float_as_uint(e);
    u = (u & 0x80000000u) ? ~u : (u | 0x80000000u);  // monotone map
    g_e[i] = e;
    g_key[i] = ((ull)u << 32) | (unsigned)i;
    g_rank[i] = 0;
}

__global__ void __launch_bounds__(32) rank_kernel() {
    const int lane = threadIdx.x;
    const int r0 = (blockIdx.x / CHUNKS_R) * ROWS_R;
    const int p0 = (blockIdx.x % CHUNKS_R) * (NV / CHUNKS_R);

    ull ko[ROWS_R];
    int cnt[ROWS_R];
#pragma unroll
    for (int m = 0; m < ROWS_R; m++) { ko[m] = g_key[r0 + m]; cnt[m] = 0; }

#pragma unroll 4
    for (int t = 0; t < NV / CHUNKS_R / 32; t++) {
        ull kp = __ldg(&g_key[p0 + lane + t * 32]);
#pragma unroll
        for (int m = 0; m < ROWS_R; m++) cnt[m] += (kp < ko[m]);
    }

#pragma unroll
    for (int m = 0; m < ROWS_R; m++)
        cnt[m] = __reduce_add_sync(0xffffffffu, cnt[m]);

    if (lane < ROWS_R) atomicAdd(&g_rank[r0 + lane], cnt[lane]);
}

__global__ void scatter_kernel(const float* __restrict__ log_h,
                               const int* __restrict__ events) {
    int o = blockIdx.x * blockDim.x + threadIdx.x;
    if (o >= NV) return;
    int r = g_rank[o];
    g_es[r] = g_e[o];
    g_ev[o] = (float)__ldg(&events[r]);
    g_th[o] = __ldg(&log_h[r]);
}

// 1 warp per block; 8 rows (4 packed pairs) x 1/4 of the columns per block.
__global__ void __launch_bounds__(32) pair_kernel() {
    const int lane  = threadIdx.x;
    const int chunk = blockIdx.x & (CHUNKS_P - 1);
    const int r     = (blockIdx.x / CHUNKS_P) * ROWS_P;
    const int j0    = chunk * (NV / CHUNKS_P);

    ull er2[4], c2[4], sv2[4];
#pragma unroll
    for (int m = 0; m < 4; m++) {
        er2[m] = pk(g_es[r + 2 * m], g_es[r + 2 * m + 1]);
        c2[m] = 0;
        sv2[m] = 0;
    }

    const float NEXP = -0.72134752044448f;   // -0.5 * log2(e)
    const ull NEXP2 = pk(NEXP, NEXP);
    const ull A2    = pk(0.2316419f, 0.2316419f);
    const ull ONE2  = pk(1.0f, 1.0f);
    // Zelen-Severo coefficients, NEGATED (s = fma(ex, t*p, 0.5) = 0.5 - q >= 0)
    const ull B5n = pk(-0.530702685f, -0.530702685f);
    const ull B4n = pk( 0.726576002f,  0.726576002f);
    const ull B3n = pk(-0.710706864f, -0.710706864f);
    const ull B2n = pk( 0.142248367f,  0.142248367f);
    const ull B1n = pk(-0.127414794f, -0.127414794f);
    const ull HALF2 = pk(0.5f, 0.5f);
    const ull ABSM  = 0x7fffffff7fffffffULL;

#pragma unroll 2
    for (int t = 0; t < NV / CHUNKS_P / 32; t++) {
        int j = j0 + lane + t * 32;
        float ej = __ldg(&g_es[j]);
        float vj = __ldg(&g_ev[j]);
        ull nej2 = pk(-ej, -ej);
        ull vj2  = pk(vj, vj);
#pragma unroll
        for (int m = 0; m < 4; m++) {
            ull d  = add2(er2[m], nej2);          // diff (packed 2 rows)
            ull a  = mul2(mul2(d, d), NEXP2);
            float alo, ahi; unpk(alo, ahi, a);
            ull ex = pk(ex2a(alo), ex2a(ahi));    // exp(-d^2/2)
            c2[m] = fma2(ex, vj2, c2[m]);         // pdf accumulation

            ull den = fma2(d & ABSM, A2, ONE2);   // 1 + 0.2316419|d|
            float dnlo, dnhi; unpk(dnlo, dnhi, den);
            ull tt = pk(rcpa(dnlo), rcpa(dnhi));
            ull p = fma2(tt, B5n, B4n);
            p = fma2(tt, p, B3n);
            p = fma2(tt, p, B2n);
            p = fma2(tt, p, B1n);
            ull s = fma2(ex, mul2(tt, p), HALF2); // 0.5 - q,  q = 1-Phi(|d|)

            float slo, shi, dlo, dhi;
            unpk(slo, shi, s);
            unpk(dlo, dhi, d);
            sv2[m] = add2(sv2[m], pk(sgnor(slo, dlo), sgnor(shi, dhi)));
        }
    }

    float c[ROWS_P], sv[ROWS_P];
#pragma unroll
    for (int m = 0; m < 4; m++) {
        unpk(c[2 * m], c[2 * m + 1], c2[m]);
        unpk(sv[2 * m], sv[2 * m + 1], sv2[m]);
    }
#pragma unroll
    for (int k = 0; k < ROWS_P; k++) {
#pragma unroll
        for (int off = 16; off > 0; off >>= 1) {
            c[k]  += __shfl_down_sync(0xffffffffu, c[k], off);
            sv[k] += __shfl_down_sync(0xffffffffu, sv[k], off);
        }
    }

    if (lane < ROWS_P) {
        // lane k holds nothing useful; lane 0 holds the sums. Broadcast instead:
    }
    if (lane == 0) {
#pragma unroll
        for (int k = 0; k < ROWS_P; k++) {
            g_pc[chunk * NV + r + k]  = c[k];
            g_psv[chunk * NV + r + k] = sv[k];
        }
    }
}

__global__ void finalize_kernel() {
    int k = blockIdx.x * blockDim.x + threadIdx.x;
    if (k >= NV) return;
    float c = 0.0f, sv = 0.0f;
#pragma unroll
    for (int ch = 0; ch < CHUNKS_P; ch++) {
        c  += g_pc[ch * NV + k];
        sv += g_psv[ch * NV + k];
    }
    float cond = fmaf(c, 0.3989422804014327f / 8192.0f, 8.192e-29f);
    float surv = fmaf(sv, 1.0f / 8192.0f, 0.5f);
    g_rowloss[k] = (logf(cond) - logf(surv) + g_th[k]) * g_ev[k];
}

__global__ void __launch_bounds__(256) reduce_kernel(float* __restrict__ out) {
    __shared__ float sm[8];
    const int tid = threadIdx.x;
    const float4* v = (const float4*)g_rowloss;
    float a = 0.0f;
#pragma unroll
    for (int t = 0; t < NV / 4 / 256; t++) {
        float4 x = v[tid + t * 256];
        a += (x.x + x.y) + (x.z + x.w);
    }
#pragma unroll
    for (int off = 16; off > 0; off >>= 1)
        a += __shfl_down_sync(0xffffffffu, a, off);
    if ((tid & 31) == 0) sm[tid >> 5] = a;
    __syncthreads();
    if (tid == 0) {
        float s = 0.0f;
#pragma unroll
        for (int w = 0; w < 8; w++) s += sm[w];
        out[0] = -s * (1.0f / 8192.0f);
    }
}

extern "C" void kernel_launch(void* const* d_in, const int* in_sizes, int n_in,
                              void* d_out, int out_size) {
    const float* log_h  = (const float*)d_in[0];
    const float* dur    = (const float*)d_in[1];
    const int*   events = (const int*)d_in[2];
    float* out = (float*)d_out;

    prep_kernel<<<NV / 256, 256>>>(log_h, dur);
    rank_kernel<<<(NV / ROWS_R) * CHUNKS_R, 32>>>();
    scatter_kernel<<<NV / 256, 256>>>(log_h, events);
    pair_kernel<<<(NV / ROWS_P) * CHUNKS_P, 32>>>();
    finalize_kernel<<<NV / 256, 256>>>();
    reduce_kernel<<<1, 256>>>(out);
}

// round 5
// speedup vs baseline: 2.3522x; 1.0989x over previous
#include <cuda_runtime.h>
#include <math.h>

// DSAFTNKSPLLoss — n = 8192 fixed.
// prep    : e = log(dur+1e-32) - theta, sortable u64 key, zero rank counters.
// rank    : rank(o) = #{p : key_p < key_o}, 4-way column-split counting (int atomics).
// scatter : e_sorted[rank]=e, ev[o]=events[rank], th[o]=log_h[rank].
// pair_sym: SYMMETRIC O(n^2/2) kernel. Each unordered pair (i<j) computed once
//           (shared exp + Zelen-Severo cdf core), fanned out to row i and col j.
//           Upper triangle tiled as (128-row ib) x (512-col jb), ib <= 4jb+3;
//           blocks with ib >= 4jb use an i<j mask. Row partials via warp shfl;
//           col partials merged across warps in smem (fixed order) -> global.
// finalize: per element k, sum row partials (jb >= k>>9) + col partials
//           (ib <= 4(k>>9)+3, sign-flipped) + diagonal ev_k -> row loss.
// reduce  : deterministic tree reduction to the scalar loss.

#define NV 8192
#define ROWS_R 8
#define CHUNKS_R 4

typedef unsigned long long ull;

__device__ ull   g_key[NV];
__device__ int   g_rank[NV];
__device__ float g_e[NV];
__device__ float g_es[NV];
__device__ float g_ev[NV];
__device__ float g_th[NV];
__device__ float g_prow_c[16 * NV];
__device__ float g_prow_s[16 * NV];
__device__ float g_pcol_c[64 * NV];
__device__ float g_pcol_s[64 * NV];
__device__ float g_rowloss[NV];

// ---------- f32x2 helpers ----------
static __device__ __forceinline__ ull pk(float a, float b) {
    ull r; asm("mov.b64 %0, {%1, %2};" : "=l"(r) : "f"(a), "f"(b)); return r;
}
static __device__ __forceinline__ float lof(ull x) {
    return __uint_as_float((unsigned)(x & 0xffffffffu));
}
static __device__ __forceinline__ float hif(ull x) {
    return __uint_as_float((unsigned)(x >> 32));
}
static __device__ __forceinline__ ull add2(ull a, ull b) {
    ull r; asm("add.rn.f32x2 %0, %1, %2;" : "=l"(r) : "l"(a), "l"(b)); return r;
}
static __device__ __forceinline__ ull mul2(ull a, ull b) {
    ull r; asm("mul.rn.f32x2 %0, %1, %2;" : "=l"(r) : "l"(a), "l"(b)); return r;
}
static __device__ __forceinline__ ull fma2(ull a, ull b, ull c) {
    ull r; asm("fma.rn.f32x2 %0, %1, %2, %3;" : "=l"(r) : "l"(a), "l"(b), "l"(c)); return r;
}
static __device__ __forceinline__ float ex2a(float x) {
    float r; asm("ex2.approx.f32 %0, %1;" : "=f"(r) : "f"(x)); return r;
}
static __device__ __forceinline__ float rcpa(float x) {
    float r; asm("rcp.approx.f32 %0, %1;" : "=f"(r) : "f"(x)); return r;
}

__global__ void prep_kernel(const float* __restrict__ log_h,
                            const float* __restrict__ dur) {
    int i = blockIdx.x * blockDim.x + threadIdx.x;
    if (i >= NV) return;
    float e = logf(dur[i] + 1e-32f) - log_h[i];
    unsigned u = __float_as_uint(e);
    u = (u & 0x80000000u) ? ~u : (u | 0x80000000u);  // monotone map
    g_e[i] = e;
    g_key[i] = ((ull)u << 32) | (unsigned)i;
    g_rank[i] = 0;
}

__global__ void __launch_bounds__(32) rank_kernel() {
    const int lane = threadIdx.x;
    const int r0 = (blockIdx.x / CHUNKS_R) * ROWS_R;
    const int p0 = (blockIdx.x % CHUNKS_R) * (NV / CHUNKS_R);

    ull ko[ROWS_R];
    int cnt[ROWS_R];
#pragma unroll
    for (int m = 0; m < ROWS_R; m++) { ko[m] = g_key[r0 + m]; cnt[m] = 0; }

#pragma unroll 4
    for (int t = 0; t < NV / CHUNKS_R / 32; t++) {
        ull kp = __ldg(&g_key[p0 + lane + t * 32]);
#pragma unroll
        for (int m = 0; m < ROWS_R; m++) cnt[m] += (kp < ko[m]);
    }

#pragma unroll
    for (int m = 0; m < ROWS_R; m++)
        cnt[m] = __reduce_add_sync(0xffffffffu, cnt[m]);

    if (lane < ROWS_R) atomicAdd(&g_rank[r0 + lane], cnt[lane]);
}

__global__ void scatter_kernel(const float* __restrict__ log_h,
                               const int* __restrict__ events) {
    int o = blockIdx.x * blockDim.x + threadIdx.x;
    if (o >= NV) return;
    int r = g_rank[o];
    g_es[r] = g_e[o];
    g_ev[o] = (float)__ldg(&events[r]);
    g_th[o] = __ldg(&log_h[r]);
}

// ---------------- symmetric pair kernel ----------------
// Block: 8 warps; warp owns 16 rows (8 f32x2 pairs), lane owns 4 columns per
// 128-column sub-tile (4 sub-tiles cover the 512-column jb block).
template <bool MASKED>
static __device__ __forceinline__ void pair_work(int ib, int jb, int w, int lane,
                                                 int tid, float* smc, float* sms) {
    const int i0 = ib * 128 + w * 16;

    ull er2[8], evr2[8], ci2[8], svi2[8];
#pragma unroll
    for (int m = 0; m < 8; m++) {
        er2[m]  = pk(g_es[i0 + 2 * m], g_es[i0 + 2 * m + 1]);
        evr2[m] = pk(g_ev[i0 + 2 * m], g_ev[i0 + 2 * m + 1]);
        ci2[m] = 0; svi2[m] = 0;
    }

    const float NEXP = -0.72134752044448f;   // -0.5 * log2(e)
    const ull NEXP2 = pk(NEXP, NEXP);
    const ull A2    = pk(0.2316419f, 0.2316419f);
    const ull ONE2  = pk(1.0f, 1.0f);
    const ull B5n = pk(-0.530702685f, -0.530702685f);
    const ull B4n = pk( 0.726576002f,  0.726576002f);
    const ull B3n = pk(-0.710706864f, -0.710706864f);
    const ull B2n = pk( 0.142248367f,  0.142248367f);
    const ull B1n = pk(-0.127414794f, -0.127414794f);
    const ull HALF2 = pk(0.5f, 0.5f);
    const ull ABSM  = 0x7fffffff7fffffffULL;
    const ull SGNM  = 0x8000000080000000ULL;
    const ull ONEF2 = 0x3f8000003f800000ULL;

    for (int st = 0; st < 4; st++) {
        const int jbase = jb * 512 + st * 128;
        ull nej2[4], vj2[4], cj2[4], svj2[4];
        int jq[4];
#pragma unroll
        for (int q = 0; q < 4; q++) {
            int j = jbase + q * 32 + lane;
            jq[q] = j;
            float ej = __ldg(&g_es[j]);
            float vj = __ldg(&g_ev[j]);
            nej2[q] = pk(-ej, -ej);
            vj2[q]  = pk(vj, vj);
            cj2[q] = 0; svj2[q] = 0;
        }
#pragma unroll
        for (int m = 0; m < 8; m++) {
#pragma unroll
            for (int q = 0; q < 4; q++) {
                ull d  = add2(er2[m], nej2[q]);            // e_i - e_j (2 rows)
                ull a  = mul2(mul2(d, d), NEXP2);
                ull ex = pk(ex2a(lof(a)), ex2a(hif(a)));   // exp(-d^2/2)
                ull den = fma2(d & ABSM, A2, ONE2);        // 1 + 0.2316419|d|
                ull t  = pk(rcpa(lof(den)), rcpa(hif(den)));
                ull p  = fma2(t, B5n, B4n);
                p = fma2(t, p, B3n);
                p = fma2(t, p, B2n);
                p = fma2(t, p, B1n);
                ull s  = fma2(ex, mul2(t, p), HALF2);      // 0.5 - q >= 0
                ull sg = (d & SGNM) | ONEF2;               // +-1.0f per half
                if (MASKED) {
                    float mlo = (i0 + 2 * m     < jq[q]) ? 1.0f : 0.0f;
                    float mhi = (i0 + 2 * m + 1 < jq[q]) ? 1.0f : 0.0f;
                    ull m2 = pk(mlo, mhi);
                    ex = mul2(ex, m2);
                    sg = mul2(sg, m2);
                }
                ull sn = mul2(s, sg);                      // signed cdf part
                ci2[m]  = fma2(ex, vj2[q], ci2[m]);        // row i: K*ev_j
                cj2[q]  = fma2(ex, evr2[m], cj2[q]);       // col j: K*ev_i
                svi2[m] = add2(svi2[m], sn);               // row i: +sn
                svj2[q] = add2(svj2[q], sn);               // col j: -sn (flip at end)
            }
        }
        // merge column partials across the 8 warps (deterministic order)
#pragma unroll
        for (int q = 0; q < 4; q++) {
            smc[w * 128 + q * 32 + lane] = lof(cj2[q]) + hif(cj2[q]);
            sms[w * 128 + q * 32 + lane] = lof(svj2[q]) + hif(svj2[q]);
        }
        __syncthreads();
        if (tid < 128) {
            float sc = 0.0f, ss = 0.0f;
#pragma unroll
            for (int ww = 0; ww < 8; ww++) {
                sc += smc[ww * 128 + tid];
                ss += sms[ww * 128 + tid];
            }
            g_pcol_c[ib * NV + jbase + tid] = sc;
            g_pcol_s[ib * NV + jbase + tid] = ss;
        }
        __syncthreads();
    }

    // row partials: shfl-reduce across lanes (packed halves stay separate rows)
#pragma unroll
    for (int m = 0; m < 8; m++) {
#pragma unroll
        for (int off = 16; off > 0; off >>= 1) {
            ci2[m]  = add2(ci2[m],  __shfl_down_sync(0xffffffffu, ci2[m],  off));
            svi2[m] = add2(svi2[m], __shfl_down_sync(0xffffffffu, svi2[m], off));
        }
    }
    if (lane == 0) {
#pragma unroll
        for (int m = 0; m < 8; m++) {
            g_prow_c[jb * NV + i0 + 2 * m]     = lof(ci2[m]);
            g_prow_c[jb * NV + i0 + 2 * m + 1] = hif(ci2[m]);
            g_prow_s[jb * NV + i0 + 2 * m]     = lof(svi2[m]);
            g_prow_s[jb * NV + i0 + 2 * m + 1] = hif(svi2[m]);
        }
    }
}

__global__ void __launch_bounds__(256, 2) pair_sym_kernel() {
    __shared__ float smc[8 * 128];
    __shared__ float sms[8 * 128];
    const int tid = threadIdx.x;
    const int w = tid >> 5, lane = tid & 31;

    // block id -> (ib, jb) with ib in 0..4jb+3  (544 blocks total)
    int id = blockIdx.x, jb = 0;
    while (id >= 4 * jb + 4) { id -= 4 * jb + 4; jb++; }
    const int ib = id;

    if (ib >= 4 * jb) pair_work<true >(ib, jb, w, lane, tid, smc, sms);
    else              pair_work<false>(ib, jb, w, lane, tid, smc, sms);
}

__global__ void finalize_kernel() {
    int k = blockIdx.x * blockDim.x + threadIdx.x;
    if (k >= NV) return;
    float c  = g_ev[k];   // diagonal: exp(0)*ev_k
    float sv = 0.0f;      // diagonal signed part = 0
    const int jb0 = k >> 9;
    for (int jb = jb0; jb < 16; jb++) {
        c  += g_prow_c[jb * NV + k];
        sv += g_prow_s[jb * NV + k];
    }
    const int ibmax = 4 * jb0 + 3;
    for (int ibb = 0; ibb <= ibmax; ibb++) {
        c  += g_pcol_c[ibb * NV + k];
        sv -= g_pcol_s[ibb * NV + k];
    }
    float cond = fmaf(c, 0.3989422804014327f / 8192.0f, 8.192e-29f);
    float surv = fmaf(sv, 1.0f / 8192.0f, 0.5f);
    g_rowloss[k] = (logf(cond) - logf(surv) + g_th[k]) * g_ev[k];
}

__global__ void __launch_bounds__(256) reduce_kernel(float* __restrict__ out) {
    __shared__ float sm[8];
    const int tid = threadIdx.x;
    const float4* v = (const float4*)g_rowloss;
    float a = 0.0f;
#pragma unroll
    for (int t = 0; t < NV / 4 / 256; t++) {
        float4 x = v[tid + t * 256];
        a += (x.x + x.y) + (x.z + x.w);
    }
#pragma unroll
    for (int off = 16; off > 0; off >>= 1)
        a += __shfl_down_sync(0xffffffffu, a, off);
    if ((tid & 31) == 0) sm[tid >> 5] = a;
    __syncthreads();
    if (tid == 0) {
        float s = 0.0f;
#pragma unroll
        for (int w = 0; w < 8; w++) s += sm[w];
        out[0] = -s * (1.0f / 8192.0f);
    }
}

extern "C" void kernel_launch(void* const* d_in, const int* in_sizes, int n_in,
                              void* d_out, int out_size) {
    const float* log_h  = (const float*)d_in[0];
    const float* dur    = (const float*)d_in[1];
    const int*   events = (const int*)d_in[2];
    float* out = (float*)d_out;

    prep_kernel<<<NV / 256, 256>>>(log_h, dur);
    rank_kernel<<<(NV / ROWS_R) * CHUNKS_R, 32>>>();
    scatter_kernel<<<NV / 256, 256>>>(log_h, events);
    pair_sym_kernel<<<544, 256>>>();
    finalize_kernel<<<NV / 256, 256>>>();
    reduce_kernel<<<1, 256>>>(out);
}

// round 6
// speedup vs baseline: 2.4943x; 1.0604x over previous
#include <cuda_runtime.h>
#include <math.h>

// DSAFTNKSPLLoss — n = 8192 fixed.
// prep    : e = log(dur+1e-32) - theta, sortable u64 key, zero rank counters.
// rank    : rank(o) = #{p : key_p < key_o}, 4-way column-split counting (int atomics).
// scatter : e_sorted[rank]=e, ev[o]=events[rank], th[o]=log_h[rank].
// pair_sym: symmetric O(n^2/2). Because e is SORTED, for i<j the diff sign is
//           known (e_i <= e_j): no sign logic in the hot loop. Each unordered
//           pair computed once (ex2 + Zelen-Severo with d' = e_j - e_i >= 0),
//           fanned to row i and col j. Upper triangle tiled 128x512, ib<=4jb+3;
//           diagonal blocks (ib>=4jb) masked. Row partials via warp shfl; col
//           partials merged across warps in smem (fixed order).
// finalize: c_k = ev_k + rowpart + colpart; sv_k = colpart_s - rowpart_s.
// reduce  : deterministic tree reduction to the scalar loss.

#define NV 8192
#define ROWS_R 8
#define CHUNKS_R 4

typedef unsigned long long ull;

__device__ ull   g_key[NV];
__device__ int   g_rank[NV];
__device__ float g_e[NV];
__device__ float g_es[NV];
__device__ float g_ev[NV];
__device__ float g_th[NV];
__device__ float g_prow_c[16 * NV];
__device__ float g_prow_s[16 * NV];
__device__ float g_pcol_c[64 * NV];
__device__ float g_pcol_s[64 * NV];
__device__ float g_rowloss[NV];

// ---------- f32x2 helpers ----------
static __device__ __forceinline__ ull pk(float a, float b) {
    ull r; asm("mov.b64 %0, {%1, %2};" : "=l"(r) : "f"(a), "f"(b)); return r;
}
static __device__ __forceinline__ float lof(ull x) {
    return __uint_as_float((unsigned)(x & 0xffffffffu));
}
static __device__ __forceinline__ float hif(ull x) {
    return __uint_as_float((unsigned)(x >> 32));
}
static __device__ __forceinline__ ull add2(ull a, ull b) {
    ull r; asm("add.rn.f32x2 %0, %1, %2;" : "=l"(r) : "l"(a), "l"(b)); return r;
}
static __device__ __forceinline__ ull mul2(ull a, ull b) {
    ull r; asm("mul.rn.f32x2 %0, %1, %2;" : "=l"(r) : "l"(a), "l"(b)); return r;
}
static __device__ __forceinline__ ull fma2(ull a, ull b, ull c) {
    ull r; asm("fma.rn.f32x2 %0, %1, %2, %3;" : "=l"(r) : "l"(a), "l"(b), "l"(c)); return r;
}
static __device__ __forceinline__ float ex2a(float x) {
    float r; asm("ex2.approx.f32 %0, %1;" : "=f"(r) : "f"(x)); return r;
}
static __device__ __forceinline__ float rcpa(float x) {
    float r; asm("rcp.approx.f32 %0, %1;" : "=f"(r) : "f"(x)); return r;
}

__global__ void prep_kernel(const float* __restrict__ log_h,
                            const float* __restrict__ dur) {
    int i = blockIdx.x * blockDim.x + threadIdx.x;
    if (i >= NV) return;
    float e = logf(dur[i] + 1e-32f) - log_h[i];
    unsigned u = __float_as_uint(e);
    u = (u & 0x80000000u) ? ~u : (u | 0x80000000u);  // monotone map
    g_e[i] = e;
    g_key[i] = ((ull)u << 32) | (unsigned)i;
    g_rank[i] = 0;
}

__global__ void __launch_bounds__(32) rank_kernel() {
    const int lane = threadIdx.x;
    const int r0 = (blockIdx.x / CHUNKS_R) * ROWS_R;
    const int p0 = (blockIdx.x % CHUNKS_R) * (NV / CHUNKS_R);

    ull ko[ROWS_R];
    int cnt[ROWS_R];
#pragma unroll
    for (int m = 0; m < ROWS_R; m++) { ko[m] = g_key[r0 + m]; cnt[m] = 0; }

#pragma unroll 4
    for (int t = 0; t < NV / CHUNKS_R / 32; t++) {
        ull kp = __ldg(&g_key[p0 + lane + t * 32]);
#pragma unroll
        for (int m = 0; m < ROWS_R; m++) cnt[m] += (kp < ko[m]);
    }

#pragma unroll
    for (int m = 0; m < ROWS_R; m++)
        cnt[m] = __reduce_add_sync(0xffffffffu, cnt[m]);

    if (lane < ROWS_R) atomicAdd(&g_rank[r0 + lane], cnt[lane]);
}

__global__ void scatter_kernel(const float* __restrict__ log_h,
                               const int* __restrict__ events) {
    int o = blockIdx.x * blockDim.x + threadIdx.x;
    if (o >= NV) return;
    int r = g_rank[o];
    g_es[r] = g_e[o];
    g_ev[o] = (float)__ldg(&events[r]);
    g_th[o] = __ldg(&log_h[r]);
}

// ---------------- symmetric pair kernel (sorted order: d' = e_j - e_i >= 0) --
// Block: 8 warps; warp owns 16 rows (8 f32x2 pairs); lane owns 4 columns per
// 128-col sub-tile; 4 sub-tiles cover the 512-col jb block.
template <bool MASKED>
static __device__ __forceinline__ void pair_work(int ib, int jb, int w, int lane,
                                                 int tid, float* smc, float* sms) {
    const int i0 = ib * 128 + w * 16;

    ull ner2[8], evr2[8], ci2[8], svi2[8];
#pragma unroll
    for (int m = 0; m < 8; m++) {
        ner2[m] = pk(-g_es[i0 + 2 * m], -g_es[i0 + 2 * m + 1]);
        evr2[m] = pk(g_ev[i0 + 2 * m], g_ev[i0 + 2 * m + 1]);
        ci2[m] = 0; svi2[m] = 0;
    }

    const float NEXP = -0.72134752044448f;   // -0.5 * log2(e)
    const ull NEXP2 = pk(NEXP, NEXP);
    const ull A2    = pk(0.2316419f, 0.2316419f);
    const ull ONE2  = pk(1.0f, 1.0f);
    // Zelen-Severo coefficients, NEGATED (s = fma(ex, t*p, 0.5) = 0.5 - q >= 0)
    const ull B5n = pk(-0.530702685f, -0.530702685f);
    const ull B4n = pk( 0.726576002f,  0.726576002f);
    const ull B3n = pk(-0.710706864f, -0.710706864f);
    const ull B2n = pk( 0.142248367f,  0.142248367f);
    const ull B1n = pk(-0.127414794f, -0.127414794f);
    const ull HALF2 = pk(0.5f, 0.5f);
    const ull ABSM  = 0x7fffffff7fffffffULL;

    for (int st = 0; st < 4; st++) {
        const int jbase = jb * 512 + st * 128;
        ull ej2[4], vj2[4], cj2[4], svj2[4];
        int jq[4];
#pragma unroll
        for (int q = 0; q < 4; q++) {
            int j = jbase + q * 32 + lane;
            jq[q] = j;
            float ej = __ldg(&g_es[j]);
            float vj = __ldg(&g_ev[j]);
            ej2[q] = pk(ej, ej);
            vj2[q] = pk(vj, vj);
            cj2[q] = 0; svj2[q] = 0;
        }
#pragma unroll
        for (int m = 0; m < 8; m++) {
#pragma unroll
            for (int q = 0; q < 4; q++) {
                ull d  = add2(ej2[q], ner2[m]);            // e_j - e_i (>= 0 if i<j)
                ull a  = mul2(d, mul2(d, NEXP2));
                ull ex = pk(ex2a(lof(a)), ex2a(hif(a)));   // exp(-d^2/2)
                ull dp = MASKED ? (d & ABSM) : d;          // keep den positive
                ull den = fma2(dp, A2, ONE2);              // 1 + 0.2316419 d'
                ull t  = pk(rcpa(lof(den)), rcpa(hif(den)));
                ull p  = fma2(t, B5n, B4n);
                p = fma2(t, p, B3n);
                p = fma2(t, p, B2n);
                p = fma2(t, p, B1n);
                ull s  = fma2(ex, mul2(t, p), HALF2);      // 0.5 - q >= 0
                if (MASKED) {
                    ull m2 = pk((i0 + 2 * m     < jq[q]) ? 1.0f : 0.0f,
                                (i0 + 2 * m + 1 < jq[q]) ? 1.0f : 0.0f);
                    ex = mul2(ex, m2);
                    s  = mul2(s, m2);
                }
                ci2[m]  = fma2(ex, vj2[q], ci2[m]);        // row i: K*ev_j
                cj2[q]  = fma2(ex, evr2[m], cj2[q]);       // col j: K*ev_i
                svi2[m] = add2(svi2[m], s);                // row i gets -s (finalize)
                svj2[q] = add2(svj2[q], s);                // col j gets +s (finalize)
            }
        }
        // merge column partials across the 8 warps (deterministic order)
#pragma unroll
        for (int q = 0; q < 4; q++) {
            smc[w * 128 + q * 32 + lane] = lof(cj2[q]) + hif(cj2[q]);
            sms[w * 128 + q * 32 + lane] = lof(svj2[q]) + hif(svj2[q]);
        }
        __syncthreads();
        if (tid < 128) {
            float sc = 0.0f, ss = 0.0f;
#pragma unroll
            for (int ww = 0; ww < 8; ww++) {
                sc += smc[ww * 128 + tid];
                ss += sms[ww * 128 + tid];
            }
            g_pcol_c[ib * NV + jbase + tid] = sc;
            g_pcol_s[ib * NV + jbase + tid] = ss;
        }
        __syncthreads();
    }

    // row partials: shfl-reduce across lanes (packed halves stay separate rows)
#pragma unroll
    for (int m = 0; m < 8; m++) {
#pragma unroll
        for (int off = 16; off > 0; off >>= 1) {
            ci2[m]  = add2(ci2[m],  __shfl_down_sync(0xffffffffu, ci2[m],  off));
            svi2[m] = add2(svi2[m], __shfl_down_sync(0xffffffffu, svi2[m], off));
        }
    }
    if (lane == 0) {
#pragma unroll
        for (int m = 0; m < 8; m++) {
            g_prow_c[jb * NV + i0 + 2 * m]     = lof(ci2[m]);
            g_prow_c[jb * NV + i0 + 2 * m + 1] = hif(ci2[m]);
            g_prow_s[jb * NV + i0 + 2 * m]     = lof(svi2[m]);
            g_prow_s[jb * NV + i0 + 2 * m + 1] = hif(svi2[m]);
        }
    }
}

__global__ void __launch_bounds__(256, 2) pair_sym_kernel() {
    __shared__ float smc[8 * 128];
    __shared__ float sms[8 * 128];
    const int tid = threadIdx.x;
    const int w = tid >> 5, lane = tid & 31;

    // block id -> (ib, jb) with ib in 0..4jb+3  (544 blocks total)
    int id = blockIdx.x, jb = 0;
    while (id >= 4 * jb + 4) { id -= 4 * jb + 4; jb++; }
    const int ib = id;

    if (ib >= 4 * jb) pair_work<true >(ib, jb, w, lane, tid, smc, sms);
    else              pair_work<false>(ib, jb, w, lane, tid, smc, sms);
}

__global__ void finalize_kernel() {
    int k = blockIdx.x * blockDim.x + threadIdx.x;
    if (k >= NV) return;
    float c  = g_ev[k];   // diagonal: exp(0)*ev_k
    float sv = 0.0f;      // diagonal signed part = 0
    const int jb0 = k >> 9;
    for (int jb = jb0; jb < 16; jb++) {
        c  += g_prow_c[jb * NV + k];
        sv -= g_prow_s[jb * NV + k];   // row role: cdf - 0.5 = -s
    }
    const int ibmax = 4 * jb0 + 3;
    for (int ibb = 0; ibb <= ibmax; ibb++) {
        c  += g_pcol_c[ibb * NV + k];
        sv += g_pcol_s[ibb * NV + k];  // col role: cdf - 0.5 = +s
    }
    float cond = fmaf(c, 0.3989422804014327f / 8192.0f, 8.192e-29f);
    float surv = fmaf(sv, 1.0f / 8192.0f, 0.5f);
    g_rowloss[k] = (logf(cond) - logf(surv) + g_th[k]) * g_ev[k];
}

__global__ void __launch_bounds__(256) reduce_kernel(float* __restrict__ out) {
    __shared__ float sm[8];
    const int tid = threadIdx.x;
    const float4* v = (const float4*)g_rowloss;
    float a = 0.0f;
#pragma unroll
    for (int t = 0; t < NV / 4 / 256; t++) {
        float4 x = v[tid + t * 256];
        a += (x.x + x.y) + (x.z + x.w);
    }
#pragma unroll
    for (int off = 16; off > 0; off >>= 1)
        a += __shfl_down_sync(0xffffffffu, a, off);
    if ((tid & 31) == 0) sm[tid >> 5] = a;
    __syncthreads();
    if (tid == 0) {
        float s = 0.0f;
#pragma unroll
        for (int w = 0; w < 8; w++) s += sm[w];
        out[0] = -s * (1.0f / 8192.0f);
    }
}

extern "C" void kernel_launch(void* const* d_in, const int* in_sizes, int n_in,
                              void* d_out, int out_size) {
    const float* log_h  = (const float*)d_in[0];
    const float* dur    = (const float*)d_in[1];
    const int*   events = (const int*)d_in[2];
    float* out = (float*)d_out;

    prep_kernel<<<NV / 256, 256>>>(log_h, dur);
    rank_kernel<<<(NV / ROWS_R) * CHUNKS_R, 32>>>();
    scatter_kernel<<<NV / 256, 256>>>(log_h, events);
    pair_sym_kernel<<<544, 256>>>();
    finalize_kernel<<<NV / 256, 256>>>();
    reduce_kernel<<<1, 256>>>(out);
}

// round 7
// speedup vs baseline: 2.6075x; 1.0454x over previous
#include <cuda_runtime.h>
#include <math.h>

// DSAFTNKSPLLoss — n = 8192 fixed.
// prep    : e = log(dur+1e-32) - theta, sortable u64 key, zero rank counters.
// rank    : rank(o) = #{p : key_p < key_o}, 4-way column-split counting (int atomics).
// scatter : e_sorted[rank]=e, ev[o]=events[rank], th[o]=log_h[rank].
// pair_sym: symmetric O(n^2/2), sorted order => d = e_j - e_i >= 0 for i<j (no
//           sign logic). cdf tail via A&S 26.2.16 (3-term, |eps|<=1e-5) reusing
//           exp(-d^2/2). Tiles 64 rows x 512 cols, ib <= 8jb+7 (1088 blocks);
//           diagonal tiles (ib >= 8jb) masked. Row partials via warp shfl; col
//           partials merged across the 8 warps in smem (fixed order).
// finalize: c_k = ev_k + rowpart + colpart; sv_k = colpart_s - rowpart_s.
// reduce  : deterministic tree reduction to the scalar loss.

#define NV 8192
#define ROWS_R 8
#define CHUNKS_R 4

typedef unsigned long long ull;

__device__ ull   g_key[NV];
__device__ int   g_rank[NV];
__device__ float g_e[NV];
__device__ float g_es[NV];
__device__ float g_ev[NV];
__device__ float g_th[NV];
__device__ float g_prow_c[16 * NV];    // [jb][i]
__device__ float g_prow_s[16 * NV];
__device__ float g_pcol_c[128 * NV];   // [ib][j]
__device__ float g_pcol_s[128 * NV];
__device__ float g_rowloss[NV];

// ---------- f32x2 helpers ----------
static __device__ __forceinline__ ull pk(float a, float b) {
    ull r; asm("mov.b64 %0, {%1, %2};" : "=l"(r) : "f"(a), "f"(b)); return r;
}
static __device__ __forceinline__ float lof(ull x) {
    return __uint_as_float((unsigned)(x & 0xffffffffu));
}
static __device__ __forceinline__ float hif(ull x) {
    return __uint_as_float((unsigned)(x >> 32));
}
static __device__ __forceinline__ ull add2(ull a, ull b) {
    ull r; asm("add.rn.f32x2 %0, %1, %2;" : "=l"(r) : "l"(a), "l"(b)); return r;
}
static __device__ __forceinline__ ull mul2(ull a, ull b) {
    ull r; asm("mul.rn.f32x2 %0, %1, %2;" : "=l"(r) : "l"(a), "l"(b)); return r;
}
static __device__ __forceinline__ ull fma2(ull a, ull b, ull c) {
    ull r; asm("fma.rn.f32x2 %0, %1, %2, %3;" : "=l"(r) : "l"(a), "l"(b), "l"(c)); return r;
}
static __device__ __forceinline__ float ex2a(float x) {
    float r; asm("ex2.approx.f32 %0, %1;" : "=f"(r) : "f"(x)); return r;
}
static __device__ __forceinline__ float rcpa(float x) {
    float r; asm("rcp.approx.f32 %0, %1;" : "=f"(r) : "f"(x)); return r;
}

__global__ void prep_kernel(const float* __restrict__ log_h,
                            const float* __restrict__ dur) {
    int i = blockIdx.x * blockDim.x + threadIdx.x;
    if (i >= NV) return;
    float e = logf(dur[i] + 1e-32f) - log_h[i];
    unsigned u = __float_as_uint(e);
    u = (u & 0x80000000u) ? ~u : (u | 0x80000000u);  // monotone map
    g_e[i] = e;
    g_key[i] = ((ull)u << 32) | (unsigned)i;
    g_rank[i] = 0;
}

__global__ void __launch_bounds__(32) rank_kernel() {
    const int lane = threadIdx.x;
    const int r0 = (blockIdx.x / CHUNKS_R) * ROWS_R;
    const int p0 = (blockIdx.x % CHUNKS_R) * (NV / CHUNKS_R);

    ull ko[ROWS_R];
    int cnt[ROWS_R];
#pragma unroll
    for (int m = 0; m < ROWS_R; m++) { ko[m] = g_key[r0 + m]; cnt[m] = 0; }

    const ulonglong2* kp2 = (const ulonglong2*)&g_key[p0];
#pragma unroll 4
    for (int t = 0; t < NV / CHUNKS_R / 64; t++) {
        ulonglong2 kp = __ldg(&kp2[lane + t * 32]);
#pragma unroll
        for (int m = 0; m < ROWS_R; m++) {
            cnt[m] += (kp.x < ko[m]);
            cnt[m] += (kp.y < ko[m]);
        }
    }

#pragma unroll
    for (int m = 0; m < ROWS_R; m++)
        cnt[m] = __reduce_add_sync(0xffffffffu, cnt[m]);

    if (lane < ROWS_R) atomicAdd(&g_rank[r0 + lane], cnt[lane]);
}

__global__ void scatter_kernel(const float* __restrict__ log_h,
                               const int* __restrict__ events) {
    int o = blockIdx.x * blockDim.x + threadIdx.x;
    if (o >= NV) return;
    int r = g_rank[o];
    g_es[r] = g_e[o];
    g_ev[o] = (float)__ldg(&events[r]);
    g_th[o] = __ldg(&log_h[r]);
}

// ---------------- symmetric pair kernel ----------------
// Block: 8 warps; warp owns 8 rows (4 f32x2 pairs); lane owns 4 columns per
// 128-col sub-tile; 4 sub-tiles cover the 512-col jb block.
template <bool MASKED>
static __device__ __forceinline__ void pair_work(int ib, int jb, int w, int lane,
                                                 int tid, float* smc, float* sms) {
    const int i0 = ib * 64 + w * 8;

    ull ner2[4], evr2[4], ci2[4], svi2[4];
#pragma unroll
    for (int m = 0; m < 4; m++) {
        ner2[m] = pk(-g_es[i0 + 2 * m], -g_es[i0 + 2 * m + 1]);
        evr2[m] = pk(g_ev[i0 + 2 * m], g_ev[i0 + 2 * m + 1]);
        ci2[m] = 0; svi2[m] = 0;
    }

    const float NEXP = -0.72134752044448f;   // -0.5 * log2(e)
    const ull NEXP2 = pk(NEXP, NEXP);
    const ull A2    = pk(0.33267f, 0.33267f);
    const ull ONE2  = pk(1.0f, 1.0f);
    // A&S 26.2.16, 1/sqrt(2pi) folded, NEGATED: pn = -(a1' + a2' t + a3' t^2)
    const ull C3n = pk(-0.37392780f, -0.37392780f);
    const ull C2n = pk( 0.04793993f,  0.04793993f);
    const ull C1n = pk(-0.17401208f, -0.17401208f);
    const ull HALF2 = pk(0.5f, 0.5f);
    const ull ABSM  = 0x7fffffff7fffffffULL;

    for (int st = 0; st < 4; st++) {
        const int jbase = jb * 512 + st * 128;
        ull ej2[4], vj2[4], cj2[4], svj2[4];
        int jq[4];
#pragma unroll
        for (int q = 0; q < 4; q++) {
            int j = jbase + q * 32 + lane;
            jq[q] = j;
            float ej = __ldg(&g_es[j]);
            float vj = __ldg(&g_ev[j]);
            ej2[q] = pk(ej, ej);
            vj2[q] = pk(vj, vj);
            cj2[q] = 0; svj2[q] = 0;
        }
#pragma unroll
        for (int m = 0; m < 4; m++) {
#pragma unroll
            for (int q = 0; q < 4; q++) {
                ull d  = add2(ej2[q], ner2[m]);            // e_j - e_i (>=0 if i<j)
                ull a  = mul2(d, mul2(d, NEXP2));
                ull ex = pk(ex2a(lof(a)), ex2a(hif(a)));   // exp(-d^2/2)
                ull dp = MASKED ? (d & ABSM) : d;          // keep den positive
                ull den = fma2(dp, A2, ONE2);              // 1 + 0.33267 d
                ull t  = pk(rcpa(lof(den)), rcpa(hif(den)));
                ull p  = fma2(t, C3n, C2n);
                p = fma2(t, p, C1n);
                ull s  = fma2(ex, mul2(t, p), HALF2);      // 0.5 - q >= 0
                if (MASKED) {
                    ull m2 = pk((i0 + 2 * m     < jq[q]) ? 1.0f : 0.0f,
                                (i0 + 2 * m + 1 < jq[q]) ? 1.0f : 0.0f);
                    ex = mul2(ex, m2);
                    s  = mul2(s, m2);
                }
                ci2[m]  = fma2(ex, vj2[q], ci2[m]);        // row i: K*ev_j
                cj2[q]  = fma2(ex, evr2[m], cj2[q]);       // col j: K*ev_i
                svi2[m] = add2(svi2[m], s);                // row i gets -s (finalize)
                svj2[q] = add2(svj2[q], s);                // col j gets +s (finalize)
            }
        }
        // merge column partials across the 8 warps (deterministic order)
#pragma unroll
        for (int q = 0; q < 4; q++) {
            smc[w * 128 + q * 32 + lane] = lof(cj2[q]) + hif(cj2[q]);
            sms[w * 128 + q * 32 + lane] = lof(svj2[q]) + hif(svj2[q]);
        }
        __syncthreads();
        if (tid < 128) {
            float sc = 0.0f, ss = 0.0f;
#pragma unroll
            for (int ww = 0; ww < 8; ww++) {
                sc += smc[ww * 128 + tid];
                ss += sms[ww * 128 + tid];
            }
            g_pcol_c[ib * NV + jbase + tid] = sc;
            g_pcol_s[ib * NV + jbase + tid] = ss;
        }
        __syncthreads();
    }

    // row partials: shfl-reduce across lanes (packed halves stay separate rows)
#pragma unroll
    for (int m = 0; m < 4; m++) {
#pragma unroll
        for (int off = 16; off > 0; off >>= 1) {
            ci2[m]  = add2(ci2[m],  __shfl_down_sync(0xffffffffu, ci2[m],  off));
            svi2[m] = add2(svi2[m], __shfl_down_sync(0xffffffffu, svi2[m], off));
        }
    }
    if (lane == 0) {
#pragma unroll
        for (int m = 0; m < 4; m++) {
            g_prow_c[jb * NV + i0 + 2 * m]     = lof(ci2[m]);
            g_prow_c[jb * NV + i0 + 2 * m + 1] = hif(ci2[m]);
            g_prow_s[jb * NV + i0 + 2 * m]     = lof(svi2[m]);
            g_prow_s[jb * NV + i0 + 2 * m + 1] = hif(svi2[m]);
        }
    }
}

__global__ void __launch_bounds__(256, 3) pair_sym_kernel() {
    __shared__ float smc[8 * 128];
    __shared__ float sms[8 * 128];
    const int tid = threadIdx.x;
    const int w = tid >> 5, lane = tid & 31;

    // block id -> (ib, jb) with ib in 0..8jb+7  (1088 blocks total)
    int id = blockIdx.x, jb = 0;
    while (id >= 8 * jb + 8) { id -= 8 * jb + 8; jb++; }
    const int ib = id;

    if (ib >= 8 * jb) pair_work<true >(ib, jb, w, lane, tid, smc, sms);
    else              pair_work<false>(ib, jb, w, lane, tid, smc, sms);
}

__global__ void finalize_kernel() {
    int k = blockIdx.x * blockDim.x + threadIdx.x;
    if (k >= NV) return;
    float c  = g_ev[k];   // diagonal: exp(0)*ev_k
    float sv = 0.0f;      // diagonal signed part = 0
    const int jb0 = k >> 9;
    for (int jb = jb0; jb < 16; jb++) {
        c  += g_prow_c[jb * NV + k];
        sv -= g_prow_s[jb * NV + k];   // row role: cdf - 0.5 = -s
    }
    const int ibmax = 8 * jb0 + 7;
    for (int ibb = 0; ibb <= ibmax; ibb++) {
        c  += g_pcol_c[ibb * NV + k];
        sv += g_pcol_s[ibb * NV + k];  // col role: cdf - 0.5 = +s
    }
    float cond = fmaf(c, 0.3989422804014327f / 8192.0f, 8.192e-29f);
    float surv = fmaf(sv, 1.0f / 8192.0f, 0.5f);
    g_rowloss[k] = (logf(cond) - logf(surv) + g_th[k]) * g_ev[k];
}

__global__ void __launch_bounds__(256) reduce_kernel(float* __restrict__ out) {
    __shared__ float sm[8];
    const int tid = threadIdx.x;
    const float4* v = (const float4*)g_rowloss;
    float a = 0.0f;
#pragma unroll
    for (int t = 0; t < NV / 4 / 256; t++) {
        float4 x = v[tid + t * 256];
        a += (x.x + x.y) + (x.z + x.w);
    }
#pragma unroll
    for (int off = 16; off > 0; off >>= 1)
        a += __shfl_down_sync(0xffffffffu, a, off);
    if ((tid & 31) == 0) sm[tid >> 5] = a;
    __syncthreads();
    if (tid == 0) {
        float s = 0.0f;
#pragma unroll
        for (int w = 0; w < 8; w++) s += sm[w];
        out[0] = -s * (1.0f / 8192.0f);
    }
}

extern "C" void kernel_launch(void* const* d_in, const int* in_sizes, int n_in,
                              void* d_out, int out_size) {
    const float* log_h  = (const float*)d_in[0];
    const float* dur    = (const float*)d_in[1];
    const int*   events = (const int*)d_in[2];
    float* out = (float*)d_out;

    prep_kernel<<<NV / 256, 256>>>(log_h, dur);
    rank_kernel<<<(NV / ROWS_R) * CHUNKS_R, 32>>>();
    scatter_kernel<<<NV / 256, 256>>>(log_h, events);
    pair_sym_kernel<<<1088, 256>>>();
    finalize_kernel<<<NV / 256, 256>>>();
    reduce_kernel<<<1, 256>>>(out);
}